// round 5
// baseline (speedup 1.0000x reference)
#include <cuda_runtime.h>
#include <cuda_bf16.h>
#include <cstdint>
#include <cstddef>

#define N_NODES 50000
#define HD      128
#define NB      8
#define NR      16
#define NE      640000

// Scratch (device globals — no allocation allowed in kernel_launch).
__device__ float g_Hb[(size_t)N_NODES * NB * HD];   // 204.8 MB: Hb[n][b*128+o]
__device__ float g_h1[(size_t)N_NODES * HD];        // 25.6 MB: layer-1 output (pre-ReLU)

// ---------------------------------------------------------------------------
// bf16 two-term split: x = hi + lo with |err| ~ 2^-16 * |x|
// ---------------------------------------------------------------------------
__device__ __forceinline__ void split_bf16(float x, __nv_bfloat16& hi, __nv_bfloat16& lo)
{
    hi = __float2bfloat16_rn(x);
    lo = __float2bfloat16_rn(x - __bfloat162float(hi));
}

__device__ __forceinline__ void mma16816(float c[4],
                                         uint32_t a0, uint32_t a1, uint32_t a2, uint32_t a3,
                                         uint32_t b0, uint32_t b1)
{
    asm volatile(
        "mma.sync.aligned.m16n8k16.row.col.f32.bf16.bf16.f32 "
        "{%0,%1,%2,%3}, {%4,%5,%6,%7}, {%8,%9}, {%0,%1,%2,%3};\n"
        : "+f"(c[0]), "+f"(c[1]), "+f"(c[2]), "+f"(c[3])
        : "r"(a0), "r"(a1), "r"(a2), "r"(a3), "r"(b0), "r"(b1));
}

// ---------------------------------------------------------------------------
// Tensor-core GEMM: Hb[n][b*128+o] = sum_k act(A[n][k]) * basis[b][k][o]
// Block: 256 threads (8 warps, 2x4), tile 128(M) x 128(N), one basis per
// blockIdx.y, K=128 in chunks of 32. bf16 split -> 3 mma products per step.
// Warp tile 64x32 (4 m-tiles x 4 n-tiles of m16n8k16).
// ---------------------------------------------------------------------------
template <bool RELU_IN>
__global__ __launch_bounds__(256) void gemm_hb_mma(
    const float* __restrict__ A, const float* __restrict__ basis,
    float* __restrict__ Hb)
{
    constexpr int PK = 40;  // padded k-stride (bf16 units): 80B = 20 words -> conflict-free frags
    __shared__ __nv_bfloat16 sa_hi[128 * PK];
    __shared__ __nv_bfloat16 sa_lo[128 * PK];
    __shared__ __nv_bfloat16 sw_hi[128 * PK];   // W transposed: [n][k]
    __shared__ __nv_bfloat16 sw_lo[128 * PK];

    const int b    = blockIdx.y;
    const int n0   = blockIdx.x * 128;
    const int tid  = threadIdx.x;
    const int warp = tid >> 5, lane = tid & 31;
    const int wm   = warp >> 2;          // 0..1  (m direction, 64 rows each)
    const int wn   = warp & 3;           // 0..3  (n direction, 32 cols each)
    const int g    = lane >> 2, t = lane & 3;

    float c[4][4][4];
#pragma unroll
    for (int mt = 0; mt < 4; mt++)
#pragma unroll
        for (int nt = 0; nt < 4; nt++)
#pragma unroll
            for (int q = 0; q < 4; q++) c[mt][nt][q] = 0.f;

    const float* wsrc = basis + (size_t)b * HD * HD;

    for (int k0 = 0; k0 < HD; k0 += 32) {
        // ---- load + split A chunk: 128 rows x 32 k (1024 float4 / 256 thr)
#pragma unroll
        for (int i = 0; i < 4; i++) {
            int e = tid + i * 256;
            int r = e >> 3, cc = (e & 7) * 4;
            int n = n0 + r;
            float4 v = make_float4(0.f, 0.f, 0.f, 0.f);
            if (n < N_NODES) v = *(const float4*)&A[(size_t)n * HD + k0 + cc];
            if (RELU_IN) {
                v.x = fmaxf(v.x, 0.f); v.y = fmaxf(v.y, 0.f);
                v.z = fmaxf(v.z, 0.f); v.w = fmaxf(v.w, 0.f);
            }
            float vv[4] = {v.x, v.y, v.z, v.w};
#pragma unroll
            for (int j = 0; j < 4; j++) {
                __nv_bfloat16 hi, lo;
                split_bf16(vv[j], hi, lo);
                sa_hi[r * PK + cc + j] = hi;
                sa_lo[r * PK + cc + j] = lo;
            }
        }
        // ---- load + split W chunk: 32 k x 128 o, store transposed [o][k]
#pragma unroll
        for (int i = 0; i < 4; i++) {
            int e  = tid + i * 256;
            int kk = e >> 5, oo = (e & 31) * 4;
            float4 v = *(const float4*)&wsrc[(size_t)(k0 + kk) * HD + oo];
            float vv[4] = {v.x, v.y, v.z, v.w};
#pragma unroll
            for (int j = 0; j < 4; j++) {
                __nv_bfloat16 hi, lo;
                split_bf16(vv[j], hi, lo);
                sw_hi[(oo + j) * PK + kk] = hi;
                sw_lo[(oo + j) * PK + kk] = lo;
            }
        }
        __syncthreads();

#pragma unroll
        for (int ks = 0; ks < 32; ks += 16) {
            uint32_t ah[4][4], al[4][4];
#pragma unroll
            for (int mt = 0; mt < 4; mt++) {
                int row = wm * 64 + mt * 16 + g;
                ah[mt][0] = *(const uint32_t*)&sa_hi[row * PK + ks + 2 * t];
                ah[mt][1] = *(const uint32_t*)&sa_hi[(row + 8) * PK + ks + 2 * t];
                ah[mt][2] = *(const uint32_t*)&sa_hi[row * PK + ks + 2 * t + 8];
                ah[mt][3] = *(const uint32_t*)&sa_hi[(row + 8) * PK + ks + 2 * t + 8];
                al[mt][0] = *(const uint32_t*)&sa_lo[row * PK + ks + 2 * t];
                al[mt][1] = *(const uint32_t*)&sa_lo[(row + 8) * PK + ks + 2 * t];
                al[mt][2] = *(const uint32_t*)&sa_lo[row * PK + ks + 2 * t + 8];
                al[mt][3] = *(const uint32_t*)&sa_lo[(row + 8) * PK + ks + 2 * t + 8];
            }
            uint32_t bh[4][2], bl[4][2];
#pragma unroll
            for (int nt = 0; nt < 4; nt++) {
                int coln = wn * 32 + nt * 8 + g;
                bh[nt][0] = *(const uint32_t*)&sw_hi[coln * PK + ks + 2 * t];
                bh[nt][1] = *(const uint32_t*)&sw_hi[coln * PK + ks + 2 * t + 8];
                bl[nt][0] = *(const uint32_t*)&sw_lo[coln * PK + ks + 2 * t];
                bl[nt][1] = *(const uint32_t*)&sw_lo[coln * PK + ks + 2 * t + 8];
            }
#pragma unroll
            for (int mt = 0; mt < 4; mt++)
#pragma unroll
                for (int nt = 0; nt < 4; nt++) {
                    mma16816(c[mt][nt], ah[mt][0], ah[mt][1], ah[mt][2], ah[mt][3],
                             bh[nt][0], bh[nt][1]);
                    mma16816(c[mt][nt], al[mt][0], al[mt][1], al[mt][2], al[mt][3],
                             bh[nt][0], bh[nt][1]);
                    mma16816(c[mt][nt], ah[mt][0], ah[mt][1], ah[mt][2], ah[mt][3],
                             bl[nt][0], bl[nt][1]);
                }
        }
        __syncthreads();
    }

    // ---- epilogue: C layout c0,c1 -> (row g, cols 2t,2t+1); c2,c3 -> row g+8
#pragma unroll
    for (int mt = 0; mt < 4; mt++) {
#pragma unroll
        for (int nt = 0; nt < 4; nt++) {
            int n = n0 + wm * 64 + mt * 16 + g;
            int o = wn * 32 + nt * 8 + t * 2;
            if (n < N_NODES) {
                float2 v = make_float2(c[mt][nt][0], c[mt][nt][1]);
                *(float2*)&Hb[(size_t)n * (NB * HD) + b * HD + o] = v;
            }
            int n2 = n + 8;
            if (n2 < N_NODES) {
                float2 v = make_float2(c[mt][nt][2], c[mt][nt][3]);
                *(float2*)&Hb[(size_t)n2 * (NB * HD) + b * HD + o] = v;
            }
        }
    }
}

// ---------------------------------------------------------------------------
// out[n][o] = bias[o]  (initialize accumulation target)
// ---------------------------------------------------------------------------
__global__ void init_bias_kernel(float* __restrict__ out,
                                 const float* __restrict__ bias)
{
    int idx = blockIdx.x * blockDim.x + threadIdx.x;
    if (idx < N_NODES * HD) out[idx] = bias[idx & (HD - 1)];
}

// ---------------------------------------------------------------------------
// Edge kernel: one warp per edge.
//   acc[o] = sum_b coef[et][b] * Hb[src][b*128+o];  atomicAdd(out[dst], acc*norm)
// ---------------------------------------------------------------------------
__global__ __launch_bounds__(256) void edge_kernel(
    const float* __restrict__ Hb, const float* __restrict__ coef,
    const float* __restrict__ norm, const int* __restrict__ src,
    const int* __restrict__ dst, const int* __restrict__ et,
    float* __restrict__ out)
{
    int warp = blockIdx.x * (blockDim.x >> 5) + (threadIdx.x >> 5);
    int lane = threadIdx.x & 31;
    if (warp >= NE) return;

    int   s  = __ldg(&src[warp]);
    int   d  = __ldg(&dst[warp]);
    int   r  = __ldg(&et[warp]);
    float nm = __ldg(&norm[warp]);

    const float* hp = Hb + (size_t)s * (NB * HD) + lane * 4;

    float ax = 0.f, ay = 0.f, az = 0.f, aw = 0.f;
#pragma unroll
    for (int b = 0; b < NB; b++) {
        float  cc = __ldg(&coef[r * NB + b]);
        float4 v  = *reinterpret_cast<const float4*>(hp + b * HD);
        ax = fmaf(cc, v.x, ax);
        ay = fmaf(cc, v.y, ay);
        az = fmaf(cc, v.z, az);
        aw = fmaf(cc, v.w, aw);
    }

    float* op = out + (size_t)d * HD + lane * 4;
    atomicAdd(op + 0, ax * nm);
    atomicAdd(op + 1, ay * nm);
    atomicAdd(op + 2, az * nm);
    atomicAdd(op + 3, aw * nm);
}

// ---------------------------------------------------------------------------
// kernel_launch
// Inputs: 0:h 1:norm 2:src 3:dst 4:etype 5:V1 6:coef1 7:bias1 8:V2 9:coef2 10:bias2
// ---------------------------------------------------------------------------
extern "C" void kernel_launch(void* const* d_in, const int* in_sizes, int n_in,
                              void* d_out, int out_size)
{
    const float* h     = (const float*)d_in[0];
    const float* norm  = (const float*)d_in[1];
    const int*   src   = (const int*)d_in[2];
    const int*   dst   = (const int*)d_in[3];
    const int*   etype = (const int*)d_in[4];
    const float* V1    = (const float*)d_in[5];
    const float* coef1 = (const float*)d_in[6];
    const float* bias1 = (const float*)d_in[7];
    const float* V2    = (const float*)d_in[8];
    const float* coef2 = (const float*)d_in[9];
    const float* bias2 = (const float*)d_in[10];
    float*       out   = (float*)d_out;

    float* Hb;  cudaGetSymbolAddress((void**)&Hb, g_Hb);
    float* h1;  cudaGetSymbolAddress((void**)&h1, g_h1);

    dim3 gemm_grid((N_NODES + 127) / 128, NB);
    int  nh_elems  = N_NODES * HD;
    int  elem_grid = (nh_elems + 255) / 256;
    int  edge_grid = (NE + 7) / 8;   // 8 warps (edges) per 256-thread block

    // ---- Layer 1: h1 = scatter(gather(h @ V1) * coef1 * norm) + bias1   (ReLU fused into L2 GEMM)
    gemm_hb_mma<false><<<gemm_grid, 256>>>(h, V1, Hb);
    init_bias_kernel<<<elem_grid, 256>>>(h1, bias1);
    edge_kernel<<<edge_grid, 256>>>(Hb, coef1, norm, src, dst, etype, h1);

    // ---- Layer 2: out = scatter(gather(relu(h1) @ V2) * coef2 * norm) + bias2
    gemm_hb_mma<true><<<gemm_grid, 256>>>(h1, V2, Hb);
    init_bias_kernel<<<elem_grid, 256>>>(out, bias2);
    edge_kernel<<<edge_grid, 256>>>(Hb, coef2, norm, src, dst, etype, out);
}

// round 7
// speedup vs baseline: 1.4095x; 1.4095x over previous
#include <cuda_runtime.h>
#include <cuda_bf16.h>
#include <cstdint>
#include <cstddef>

#define N_NODES 50000
#define HD      128
#define NB      8
#define NR      16
#define NE      640000
#define TILE_M  128
#define MAX_TILES (NE / TILE_M + NR)          // 5016
#define HB_EDGES  8192
#define NHB ((NE + HB_EDGES - 1) / HB_EDGES)  // 79
#define PK 136   // padded smem k-stride (bf16 units) -> conflict-free frag loads

// ---------------- scratch (device globals; no allocs allowed) ----------------
__device__ __nv_bfloat16 g_h_hi[(size_t)N_NODES * HD];   // 12.8 MB
__device__ __nv_bfloat16 g_h_lo[(size_t)N_NODES * HD];   // 12.8 MB
__device__ __nv_bfloat16 g_w_hi[(size_t)NR * HD * HD];   // [r][o][k] 512 KB
__device__ __nv_bfloat16 g_w_lo[(size_t)NR * HD * HD];
__device__ float g_h1[(size_t)N_NODES * HD];             // layer-1 output
__device__ int  g_sorted[NE];
__device__ int  g_hist[NR];
__device__ int  g_cursor[NR];
__device__ int4 g_tiles[MAX_TILES];                      // {rel, start, cnt, 0}
__device__ int  g_ntiles;

// ---------------------------------------------------------------------------
__device__ __forceinline__ void cp_async16(void* s, const void* g)
{
    uint32_t sa = (uint32_t)__cvta_generic_to_shared(s);
    asm volatile("cp.async.ca.shared.global [%0], [%1], 16;\n" :: "r"(sa), "l"(g));
}

__device__ __forceinline__ void mma16816(float c[4],
                                         uint32_t a0, uint32_t a1, uint32_t a2, uint32_t a3,
                                         uint32_t b0, uint32_t b1)
{
    asm volatile(
        "mma.sync.aligned.m16n8k16.row.col.f32.bf16.bf16.f32 "
        "{%0,%1,%2,%3}, {%4,%5,%6,%7}, {%8,%9}, {%0,%1,%2,%3};\n"
        : "+f"(c[0]), "+f"(c[1]), "+f"(c[2]), "+f"(c[3])
        : "r"(a0), "r"(a1), "r"(a2), "r"(a3), "r"(b0), "r"(b1));
}

// ---------------- bucketing: counting sort of edges by relation -------------
__global__ void k_zero_hist()
{
    if (threadIdx.x < NR) g_hist[threadIdx.x] = 0;
}

__global__ __launch_bounds__(256) void k_hist(const int* __restrict__ et)
{
    __shared__ int sh[NR];
    if (threadIdx.x < NR) sh[threadIdx.x] = 0;
    __syncthreads();
    int base = blockIdx.x * HB_EDGES;
    int end  = min(base + HB_EDGES, NE);
    for (int i = base + threadIdx.x; i < end; i += 256)
        atomicAdd(&sh[et[i]], 1);
    __syncthreads();
    if (threadIdx.x < NR) atomicAdd(&g_hist[threadIdx.x], sh[threadIdx.x]);
}

__global__ __launch_bounds__(256) void k_scan_tiles()
{
    __shared__ int off[NR + 1], tb[NR + 1];
    if (threadIdx.x == 0) {
        int acc = 0, t = 0;
        for (int r = 0; r < NR; r++) {
            off[r] = acc; tb[r] = t;
            g_cursor[r] = acc;
            int c = g_hist[r];
            acc += c;
            t += (c + TILE_M - 1) / TILE_M;
        }
        off[NR] = acc; tb[NR] = t;
        g_ntiles = t;
    }
    __syncthreads();
    int nt = tb[NR];
    for (int idx = threadIdx.x; idx < nt; idx += 256) {
        int r = 0;
        while (tb[r + 1] <= idx) r++;
        int local = idx - tb[r];
        int start = off[r] + local * TILE_M;
        int cnt   = min(TILE_M, off[r + 1] - start);
        g_tiles[idx] = make_int4(r, start, cnt, 0);
    }
}

__global__ __launch_bounds__(256) void k_place(const int* __restrict__ et)
{
    __shared__ int sh[NR], sbase[NR];
    if (threadIdx.x < NR) sh[threadIdx.x] = 0;
    __syncthreads();
    int base = blockIdx.x * HB_EDGES;
    int end  = min(base + HB_EDGES, NE);
    for (int i = base + threadIdx.x; i < end; i += 256)
        atomicAdd(&sh[et[i]], 1);
    __syncthreads();
    if (threadIdx.x < NR) {
        sbase[threadIdx.x] = atomicAdd(&g_cursor[threadIdx.x], sh[threadIdx.x]);
        sh[threadIdx.x] = 0;
    }
    __syncthreads();
    for (int i = base + threadIdx.x; i < end; i += 256) {
        int r = et[i];
        int p = sbase[r] + atomicAdd(&sh[r], 1);
        g_sorted[p] = i;
    }
}

// ---------------- W[r] = coef[r]·basis, transposed [r][o][k], bf16 split ----
__global__ __launch_bounds__(256) void k_fold_w(const float* __restrict__ basis,
                                                const float* __restrict__ coef)
{
    int r = blockIdx.x;
    __shared__ float cf[NB];
    if (threadIdx.x < NB) cf[threadIdx.x] = coef[r * NB + threadIdx.x];
    __syncthreads();
    for (int e = threadIdx.x; e < HD * HD; e += 256) {
        int k = e >> 7, o = e & 127;
        float acc = 0.f;
#pragma unroll
        for (int b = 0; b < NB; b++)
            acc = fmaf(cf[b], basis[((size_t)b * HD + k) * HD + o], acc);
        __nv_bfloat16 hi = __float2bfloat16_rn(acc);
        __nv_bfloat16 lo = __float2bfloat16_rn(acc - __bfloat162float(hi));
        size_t idx = ((size_t)r * HD + o) * HD + k;
        g_w_hi[idx] = hi;
        g_w_lo[idx] = lo;
    }
}

// ---------------- split node features to bf16 hi/lo (optional ReLU) ---------
template <bool RELU>
__global__ __launch_bounds__(256) void k_split_h(const float* __restrict__ x)
{
    int idx = blockIdx.x * 256 + threadIdx.x;
    if (idx < N_NODES * HD) {
        float v = x[idx];
        if (RELU) v = fmaxf(v, 0.f);
        __nv_bfloat16 hi = __float2bfloat16_rn(v);
        g_h_hi[idx] = hi;
        g_h_lo[idx] = __float2bfloat16_rn(v - __bfloat162float(hi));
    }
}

// ---------------- out[n][o] = bias[o] ---------------------------------------
__global__ void init_bias_kernel(float* __restrict__ out,
                                 const float* __restrict__ bias)
{
    int idx = blockIdx.x * blockDim.x + threadIdx.x;
    if (idx < N_NODES * HD) out[idx] = bias[idx & (HD - 1)];
}

// ---------------------------------------------------------------------------
// Fused gather-GEMM-scatter. One block = one 128-edge tile of one relation.
//   C[128x128] = h[src_tile] @ W[r]^T   (bf16 split, 3 products)
//   atomicAdd(out[dst_i][:], C[i][:] * norm_i)
// 256 threads (8 warps 2x4), warp tile 64x32, K=128 single SMEM stage.
// ---------------------------------------------------------------------------
__global__ __launch_bounds__(256) void k_edge_gemm(
    const int* __restrict__ src, const int* __restrict__ dst,
    const float* __restrict__ norm, float* __restrict__ out)
{
    if ((int)blockIdx.x >= g_ntiles) return;
    int4 tl   = g_tiles[blockIdx.x];
    int  rel  = tl.x, start = tl.y, cnt = tl.z;

    extern __shared__ char smem[];
    __nv_bfloat16* sa_hi = (__nv_bfloat16*)smem;
    __nv_bfloat16* sa_lo = sa_hi + 128 * PK;
    __nv_bfloat16* sw_hi = sa_lo + 128 * PK;
    __nv_bfloat16* sw_lo = sw_hi + 128 * PK;
    int*   srcv  = (int*)(sw_lo + 128 * PK);
    int*   dstv  = srcv + 128;
    float* normv = (float*)(dstv + 128);

    const int tid = threadIdx.x;

    if (tid < 128) {
        if (tid < cnt) {
            int eid = g_sorted[start + tid];
            srcv[tid]  = src[eid];
            dstv[tid]  = dst[eid];
            normv[tid] = norm[eid];
        } else {
            srcv[tid] = 0; dstv[tid] = -1; normv[tid] = 0.f;
        }
    }
    __syncthreads();

    // Gather A rows (h_hi/h_lo[src]) and W rows ([r][o][k]) via cp.async.
    {
        int row  = tid >> 1, half = tid & 1;
        const __nv_bfloat16* gA = (half ? g_h_lo : g_h_hi) + (size_t)srcv[row] * HD;
        __nv_bfloat16*       sA = (half ? sa_lo : sa_hi) + row * PK;
        const __nv_bfloat16* gW = (half ? g_w_lo : g_w_hi) + ((size_t)rel * HD + row) * HD;
        __nv_bfloat16*       sW = (half ? sw_lo : sw_hi) + row * PK;
#pragma unroll
        for (int c = 0; c < 16; c++) {
            cp_async16(sA + c * 8, gA + c * 8);
            cp_async16(sW + c * 8, gW + c * 8);
        }
    }
    asm volatile("cp.async.commit_group;\n" ::: "memory");
    asm volatile("cp.async.wait_group 0;\n" ::: "memory");
    __syncthreads();

    const int warp = tid >> 5, lane = tid & 31;
    const int wm = warp >> 2, wn = warp & 3;
    const int gq = lane >> 2, t = lane & 3;

    float c[4][4][4];
#pragma unroll
    for (int mt = 0; mt < 4; mt++)
#pragma unroll
        for (int nt = 0; nt < 4; nt++)
#pragma unroll
            for (int q = 0; q < 4; q++) c[mt][nt][q] = 0.f;

#pragma unroll 2
    for (int ks = 0; ks < HD; ks += 16) {
        uint32_t ah[4][4], al[4][4];
#pragma unroll
        for (int mt = 0; mt < 4; mt++) {
            int row = wm * 64 + mt * 16 + gq;
            ah[mt][0] = *(const uint32_t*)&sa_hi[row * PK + ks + 2 * t];
            ah[mt][1] = *(const uint32_t*)&sa_hi[(row + 8) * PK + ks + 2 * t];
            ah[mt][2] = *(const uint32_t*)&sa_hi[row * PK + ks + 2 * t + 8];
            ah[mt][3] = *(const uint32_t*)&sa_hi[(row + 8) * PK + ks + 2 * t + 8];
            al[mt][0] = *(const uint32_t*)&sa_lo[row * PK + ks + 2 * t];
            al[mt][1] = *(const uint32_t*)&sa_lo[(row + 8) * PK + ks + 2 * t];
            al[mt][2] = *(const uint32_t*)&sa_lo[row * PK + ks + 2 * t + 8];
            al[mt][3] = *(const uint32_t*)&sa_lo[(row + 8) * PK + ks + 2 * t + 8];
        }
        uint32_t bh[4][2], bl[4][2];
#pragma unroll
        for (int nt = 0; nt < 4; nt++) {
            int coln = wn * 32 + nt * 8 + gq;
            bh[nt][0] = *(const uint32_t*)&sw_hi[coln * PK + ks + 2 * t];
            bh[nt][1] = *(const uint32_t*)&sw_hi[coln * PK + ks + 2 * t + 8];
            bl[nt][0] = *(const uint32_t*)&sw_lo[coln * PK + ks + 2 * t];
            bl[nt][1] = *(const uint32_t*)&sw_lo[coln * PK + ks + 2 * t + 8];
        }
#pragma unroll
        for (int mt = 0; mt < 4; mt++)
#pragma unroll
            for (int nt = 0; nt < 4; nt++) {
                mma16816(c[mt][nt], ah[mt][0], ah[mt][1], ah[mt][2], ah[mt][3],
                         bh[nt][0], bh[nt][1]);
                mma16816(c[mt][nt], al[mt][0], al[mt][1], al[mt][2], al[mt][3],
                         bh[nt][0], bh[nt][1]);
                mma16816(c[mt][nt], ah[mt][0], ah[mt][1], ah[mt][2], ah[mt][3],
                         bl[nt][0], bl[nt][1]);
            }
    }

    // Scatter epilogue: out[dst_i][o] += C[i][o] * norm_i
#pragma unroll
    for (int mt = 0; mt < 4; mt++) {
        int row0 = wm * 64 + mt * 16 + gq;
        int d0 = dstv[row0],     d1 = dstv[row0 + 8];
        float n0 = normv[row0],  n1 = normv[row0 + 8];
#pragma unroll
        for (int nt = 0; nt < 4; nt++) {
            int o = wn * 32 + nt * 8 + t * 2;
            if (d0 >= 0) {
                float* p = out + (size_t)d0 * HD + o;
                atomicAdd(p,     c[mt][nt][0] * n0);
                atomicAdd(p + 1, c[mt][nt][1] * n0);
            }
            if (d1 >= 0) {
                float* p = out + (size_t)d1 * HD + o;
                atomicAdd(p,     c[mt][nt][2] * n1);
                atomicAdd(p + 1, c[mt][nt][3] * n1);
            }
        }
    }
}

// ---------------------------------------------------------------------------
// kernel_launch
// Inputs: 0:h 1:norm 2:src 3:dst 4:etype 5:V1 6:coef1 7:bias1 8:V2 9:coef2 10:bias2
// ---------------------------------------------------------------------------
extern "C" void kernel_launch(void* const* d_in, const int* in_sizes, int n_in,
                              void* d_out, int out_size)
{
    const float* h     = (const float*)d_in[0];
    const float* norm  = (const float*)d_in[1];
    const int*   src   = (const int*)d_in[2];
    const int*   dst   = (const int*)d_in[3];
    const int*   etype = (const int*)d_in[4];
    const float* V1    = (const float*)d_in[5];
    const float* coef1 = (const float*)d_in[6];
    const float* bias1 = (const float*)d_in[7];
    const float* V2    = (const float*)d_in[8];
    const float* coef2 = (const float*)d_in[9];
    const float* bias2 = (const float*)d_in[10];
    float*       out   = (float*)d_out;

    float* h1; cudaGetSymbolAddress((void**)&h1, g_h1);

    static int smem_set = 0;
    const int GEMM_SMEM = 4 * 128 * PK * 2 + 128 * 12 + 64;   // ~140.9 KB
    if (!smem_set) {
        cudaFuncSetAttribute(k_edge_gemm,
                             cudaFuncAttributeMaxDynamicSharedMemorySize, GEMM_SMEM);
        smem_set = 1;
    }

    int nh_elems  = N_NODES * HD;
    int elem_grid = (nh_elems + 255) / 256;

    // ---- bucket edges by relation (shared by both layers)
    k_zero_hist<<<1, 32>>>();
    k_hist<<<NHB, 256>>>(etype);
    k_scan_tiles<<<1, 256>>>();
    k_place<<<NHB, 256>>>(etype);

    // ---- Layer 1
    k_fold_w<<<NR, 256>>>(V1, coef1);
    k_split_h<false><<<elem_grid, 256>>>(h);
    init_bias_kernel<<<elem_grid, 256>>>(h1, bias1);
    k_edge_gemm<<<MAX_TILES, 256, GEMM_SMEM>>>(src, dst, norm, h1);

    // ---- Layer 2
    k_fold_w<<<NR, 256>>>(V2, coef2);
    k_split_h<true><<<elem_grid, 256>>>(h1);
    init_bias_kernel<<<elem_grid, 256>>>(out, bias2);
    k_edge_gemm<<<MAX_TILES, 256, GEMM_SMEM>>>(src, dst, norm, out);
}

// round 9
// speedup vs baseline: 1.9831x; 1.4070x over previous
#include <cuda_runtime.h>
#include <cuda_fp16.h>
#include <cstdint>
#include <cstddef>

#define N_NODES 50000
#define HD      128
#define NB      8
#define NR      16
#define NE      640000
#define TILE_M  128
#define MAX_TILES (NE / TILE_M + NR)          // 5016
#define HB_EDGES  8192
#define NHB ((NE + HB_EDGES - 1) / HB_EDGES)  // 79

#define TILE_BYTES 32768                      // 128 x 128 fp16, swizzled image

// ---------------- scratch (device globals; no allocs allowed) ----------------
__device__ __half g_h_hi[(size_t)N_NODES * HD];          // 12.8 MB
__device__ __half g_h_lo[(size_t)N_NODES * HD];          // 12.8 MB
// W prepacked per relation as the exact SMEM tile image (blocked-atom SW128)
__device__ unsigned char g_w_pk[(size_t)NR * TILE_BYTES];   // 512 KB
__device__ float g_h1[(size_t)N_NODES * HD];             // layer-1 output
__device__ int  g_sorted[NE];
__device__ int  g_hist[NR];
__device__ int  g_cursor[NR];
__device__ int4 g_tiles[MAX_TILES];                      // {rel, start, cnt, 0}
__device__ int  g_ntiles;

// ---------------------------------------------------------------------------
__device__ __forceinline__ void cp_async16_s(uint32_t s, const void* g)
{
    asm volatile("cp.async.ca.shared.global [%0], [%1], 16;\n" :: "r"(s), "l"(g));
}

// Blocked-atom SW128 byte offset for element (row, k) of a [128 x 128] b16
// K-major tile: atom = 8 rows x 64 elems (1024 B); atoms tile M first (16),
// then K (2). XOR source is purely row&7 -> ldmatrix conflict-free.
__device__ __forceinline__ uint32_t toff(int row, int k)
{
    uint32_t atom = (uint32_t)((row >> 3) + (k >> 6) * 16);
    uint32_t sw   = ((uint32_t)(k & 63) * 2) ^ (((uint32_t)row & 7) << 4);
    return atom * 1024 + ((uint32_t)row & 7) * 128 + sw;
}

#define LDSM_X4(r0, r1, r2, r3, addr)                                        \
    asm volatile("ldmatrix.sync.aligned.m8n8.x4.shared.b16 {%0,%1,%2,%3}, [%4];" \
                 : "=r"(r0), "=r"(r1), "=r"(r2), "=r"(r3) : "r"(addr))

__device__ __forceinline__ void mma16816(float c[4],
                                         uint32_t a0, uint32_t a1, uint32_t a2, uint32_t a3,
                                         uint32_t b0, uint32_t b1)
{
    asm volatile(
        "mma.sync.aligned.m16n8k16.row.col.f32.f16.f16.f32 "
        "{%0,%1,%2,%3}, {%4,%5,%6,%7}, {%8,%9}, {%0,%1,%2,%3};\n"
        : "+f"(c[0]), "+f"(c[1]), "+f"(c[2]), "+f"(c[3])
        : "r"(a0), "r"(a1), "r"(a2), "r"(a3), "r"(b0), "r"(b1));
}

// ---------------- bucketing: counting sort of edges by relation -------------
__global__ void k_zero_hist()
{
    if (threadIdx.x < NR) g_hist[threadIdx.x] = 0;
}

__global__ __launch_bounds__(256) void k_hist(const int* __restrict__ et)
{
    __shared__ int sh[NR];
    if (threadIdx.x < NR) sh[threadIdx.x] = 0;
    __syncthreads();
    int base = blockIdx.x * HB_EDGES;
    int end  = min(base + HB_EDGES, NE);
    for (int i = base + threadIdx.x; i < end; i += 256)
        atomicAdd(&sh[et[i]], 1);
    __syncthreads();
    if (threadIdx.x < NR) atomicAdd(&g_hist[threadIdx.x], sh[threadIdx.x]);
}

__global__ __launch_bounds__(256) void k_scan_tiles()
{
    __shared__ int off[NR + 1], tb[NR + 1];
    if (threadIdx.x == 0) {
        int acc = 0, t = 0;
        for (int r = 0; r < NR; r++) {
            off[r] = acc; tb[r] = t;
            g_cursor[r] = acc;
            int c = g_hist[r];
            acc += c;
            t += (c + TILE_M - 1) / TILE_M;
        }
        off[NR] = acc; tb[NR] = t;
        g_ntiles = t;
    }
    __syncthreads();
    int nt = tb[NR];
    for (int idx = threadIdx.x; idx < nt; idx += 256) {
        int r = 0;
        while (tb[r + 1] <= idx) r++;
        int local = idx - tb[r];
        int start = off[r] + local * TILE_M;
        int cnt   = min(TILE_M, off[r + 1] - start);
        g_tiles[idx] = make_int4(r, start, cnt, 0);
    }
}

__global__ __launch_bounds__(256) void k_place(const int* __restrict__ et)
{
    __shared__ int sh[NR], sbase[NR];
    if (threadIdx.x < NR) sh[threadIdx.x] = 0;
    __syncthreads();
    int base = blockIdx.x * HB_EDGES;
    int end  = min(base + HB_EDGES, NE);
    for (int i = base + threadIdx.x; i < end; i += 256)
        atomicAdd(&sh[et[i]], 1);
    __syncthreads();
    if (threadIdx.x < NR) {
        sbase[threadIdx.x] = atomicAdd(&g_cursor[threadIdx.x], sh[threadIdx.x]);
        sh[threadIdx.x] = 0;
    }
    __syncthreads();
    for (int i = base + threadIdx.x; i < end; i += 256) {
        int r = et[i];
        int p = sbase[r] + atomicAdd(&sh[r], 1);
        g_sorted[p] = i;
    }
}

// ---- W[r] = coef[r]·basis, packed fp16 as swizzled [o][k] tile image -------
__global__ __launch_bounds__(256) void k_fold_w(const float* __restrict__ basis,
                                                const float* __restrict__ coef)
{
    int r = blockIdx.x;
    __shared__ float cf[NB];
    if (threadIdx.x < NB) cf[threadIdx.x] = coef[r * NB + threadIdx.x];
    __syncthreads();
    unsigned char* wp = g_w_pk + (size_t)r * TILE_BYTES;
    for (int e = threadIdx.x; e < HD * HD; e += 256) {
        int k = e >> 7, o = e & 127;
        float acc = 0.f;
#pragma unroll
        for (int b = 0; b < NB; b++)
            acc = fmaf(cf[b], basis[((size_t)b * HD + k) * HD + o], acc);
        *(__half*)(wp + toff(o, k)) = __float2half_rn(acc);
    }
}

// ---------------- split node features to fp16 hi/lo (optional ReLU) ---------
template <bool RELU>
__global__ __launch_bounds__(256) void k_split_h(const float* __restrict__ x)
{
    int idx = blockIdx.x * 256 + threadIdx.x;
    if (idx < N_NODES * HD) {
        float v = x[idx];
        if (RELU) v = fmaxf(v, 0.f);
        __half hi = __float2half_rn(v);
        g_h_hi[idx] = hi;
        g_h_lo[idx] = __float2half_rn(v - __half2float(hi));
    }
}

// ---------------- out[n][o] = bias[o] ---------------------------------------
__global__ void init_bias_kernel(float* __restrict__ out,
                                 const float* __restrict__ bias)
{
    int idx = blockIdx.x * blockDim.x + threadIdx.x;
    if (idx < N_NODES * HD) out[idx] = bias[idx & (HD - 1)];
}

// ---------------------------------------------------------------------------
// Fused gather-GEMM-scatter. One block = one 128-edge tile of one relation.
//   C[128x128] = (Ah + Al)[src_tile] @ fp16(W[rel])^T    (2 mma products)
//   atomicAdd(out[dst_i][:], C[i][:] * norm_i)
// 256 threads (8 warps 2x4), warp tile 64x32, K=128 single SMEM stage,
// SW128 blocked-atom tiles + ldmatrix.x4 fragments. 2 CTAs/SM.
// ---------------------------------------------------------------------------
__global__ __launch_bounds__(256, 2) void k_edge_gemm(
    const int* __restrict__ src, const int* __restrict__ dst,
    const float* __restrict__ norm, float* __restrict__ out)
{
    if ((int)blockIdx.x >= g_ntiles) return;
    int4 tl  = g_tiles[blockIdx.x];
    int  rel = tl.x, start = tl.y, cnt = tl.z;

    extern __shared__ char smem[];
    uint32_t base = (uint32_t)__cvta_generic_to_shared(smem);
    int*   srcv  = (int*)smem;
    int*   dstv  = (int*)(smem + 512);
    float* normv = (float*)(smem + 1024);
    uint32_t tiles_a = (base + 2048 + 1023) & ~1023u;   // 1024-aligned
    uint32_t sa_hi = tiles_a;
    uint32_t sa_lo = tiles_a + TILE_BYTES;
    uint32_t sw_t  = tiles_a + 2 * TILE_BYTES;

    const int tid  = threadIdx.x;
    const int lane = tid & 31;

    if (tid < 128) {
        if (tid < cnt) {
            int eid = g_sorted[start + tid];
            srcv[tid]  = src[eid];
            dstv[tid]  = dst[eid];
            normv[tid] = norm[eid];
        } else {
            srcv[tid] = 0; dstv[tid] = -1; normv[tid] = 0.f;
        }
    }
    __syncthreads();

    // ---- W tile: straight copy of prepacked swizzled image (32 KB)
    {
        const unsigned char* wp = g_w_pk + (size_t)rel * TILE_BYTES;
#pragma unroll
        for (int i = 0; i < 8; i++) {
            int off = tid * 16 + i * 4096;
            cp_async16_s(sw_t + off, wp + off);
        }
    }
    // ---- gather A rows into swizzled tiles (2 threads per row: hi/lo)
    {
        int row  = tid >> 1, half = tid & 1;
        const __half* gA = (half ? g_h_lo : g_h_hi) + (size_t)srcv[row] * HD;
        uint32_t      sA = half ? sa_lo : sa_hi;
#pragma unroll
        for (int c = 0; c < 16; c++)
            cp_async16_s(sA + toff(row, c * 8), gA + c * 8);
    }
    asm volatile("cp.async.commit_group;\n" ::: "memory");
    asm volatile("cp.async.wait_group 0;\n" ::: "memory");
    __syncthreads();

    const int warp = tid >> 5;
    const int wm = warp >> 2, wn = warp & 3;     // warp tile: rows wm*64, cols wn*32
    const int mid = lane >> 3, rin = lane & 7;   // ldmatrix group / row-in-group

    float c[4][4][4];
#pragma unroll
    for (int mt = 0; mt < 4; mt++)
#pragma unroll
        for (int nt = 0; nt < 4; nt++)
#pragma unroll
            for (int q = 0; q < 4; q++) c[mt][nt][q] = 0.f;

#pragma unroll
    for (int ks = 0; ks < HD; ks += 16) {
        // A fragments: groups (rows+0,k0)(rows+8,k0)(rows+0,k8)(rows+8,k8)
        uint32_t ah[4][4], al[4][4];
        int ka = ks + ((mid >> 1) << 3);
        int ra = ((mid & 1) << 3) + rin;
#pragma unroll
        for (int mt = 0; mt < 4; mt++) {
            uint32_t rel_off = toff(wm * 64 + mt * 16 + ra, ka);
            LDSM_X4(ah[mt][0], ah[mt][1], ah[mt][2], ah[mt][3], sa_hi + rel_off);
            LDSM_X4(al[mt][0], al[mt][1], al[mt][2], al[mt][3], sa_lo + rel_off);
        }
        // B fragments: groups (nt,k0)(nt,k8)(nt+1,k0)(nt+1,k8)
        uint32_t bb[2][4];
        int kb = ks + ((mid & 1) << 3);
#pragma unroll
        for (int p = 0; p < 2; p++) {
            int nc = wn * 32 + p * 16 + ((mid >> 1) << 3) + rin;
            LDSM_X4(bb[p][0], bb[p][1], bb[p][2], bb[p][3], sw_t + toff(nc, kb));
        }
#pragma unroll
        for (int mt = 0; mt < 4; mt++)
#pragma unroll
            for (int nt = 0; nt < 4; nt++) {
                uint32_t b0 = bb[nt >> 1][(nt & 1) * 2];
                uint32_t b1 = bb[nt >> 1][(nt & 1) * 2 + 1];
                mma16816(c[mt][nt], ah[mt][0], ah[mt][1], ah[mt][2], ah[mt][3], b0, b1);
                mma16816(c[mt][nt], al[mt][0], al[mt][1], al[mt][2], al[mt][3], b0, b1);
            }
    }

    // ---- scatter epilogue: out[dst_i][o] += C[i][o] * norm_i
    const int gq = lane >> 2, t = lane & 3;
#pragma unroll
    for (int mt = 0; mt < 4; mt++) {
        int row0 = wm * 64 + mt * 16 + gq;
        int d0 = dstv[row0],     d1 = dstv[row0 + 8];
        float n0 = normv[row0],  n1 = normv[row0 + 8];
#pragma unroll
        for (int nt = 0; nt < 4; nt++) {
            int o = wn * 32 + nt * 8 + t * 2;
            if (d0 >= 0) {
                float* p = out + (size_t)d0 * HD + o;
                atomicAdd(p,     c[mt][nt][0] * n0);
                atomicAdd(p + 1, c[mt][nt][1] * n0);
            }
            if (d1 >= 0) {
                float* p = out + (size_t)d1 * HD + o;
                atomicAdd(p,     c[mt][nt][2] * n1);
                atomicAdd(p + 1, c[mt][nt][3] * n1);
            }
        }
    }
}

// ---------------------------------------------------------------------------
// kernel_launch
// Inputs: 0:h 1:norm 2:src 3:dst 4:etype 5:V1 6:coef1 7:bias1 8:V2 9:coef2 10:bias2
// ---------------------------------------------------------------------------
extern "C" void kernel_launch(void* const* d_in, const int* in_sizes, int n_in,
                              void* d_out, int out_size)
{
    const float* h     = (const float*)d_in[0];
    const float* norm  = (const float*)d_in[1];
    const int*   src   = (const int*)d_in[2];
    const int*   dst   = (const int*)d_in[3];
    const int*   etype = (const int*)d_in[4];
    const float* V1    = (const float*)d_in[5];
    const float* coef1 = (const float*)d_in[6];
    const float* bias1 = (const float*)d_in[7];
    const float* V2    = (const float*)d_in[8];
    const float* coef2 = (const float*)d_in[9];
    const float* bias2 = (const float*)d_in[10];
    float*       out   = (float*)d_out;

    float* h1; cudaGetSymbolAddress((void**)&h1, g_h1);

    static int smem_set = 0;
    const int GEMM_SMEM = 2048 + 1024 + 3 * TILE_BYTES;   // ~99 KB -> 2 CTAs/SM
    if (!smem_set) {
        cudaFuncSetAttribute(k_edge_gemm,
                             cudaFuncAttributeMaxDynamicSharedMemorySize, GEMM_SMEM);
        smem_set = 1;
    }

    int nh_elems  = N_NODES * HD;
    int elem_grid = (nh_elems + 255) / 256;

    // ---- bucket edges by relation (shared by both layers)
    k_zero_hist<<<1, 32>>>();
    k_hist<<<NHB, 256>>>(etype);
    k_scan_tiles<<<1, 256>>>();
    k_place<<<NHB, 256>>>(etype);

    // ---- Layer 1
    k_fold_w<<<NR, 256>>>(V1, coef1);
    k_split_h<false><<<elem_grid, 256>>>(h);
    init_bias_kernel<<<elem_grid, 256>>>(h1, bias1);
    k_edge_gemm<<<MAX_TILES, 256, GEMM_SMEM>>>(src, dst, norm, h1);

    // ---- Layer 2
    k_fold_w<<<NR, 256>>>(V2, coef2);
    k_split_h<true><<<elem_grid, 256>>>(h1);
    init_bias_kernel<<<elem_grid, 256>>>(out, bias2);
    k_edge_gemm<<<MAX_TILES, 256, GEMM_SMEM>>>(src, dst, norm, out);
}

// round 10
// speedup vs baseline: 2.1576x; 1.0880x over previous
#include <cuda_runtime.h>
#include <cuda_fp16.h>
#include <cstdint>
#include <cstddef>

#define N_NODES 50000
#define HD      128
#define NB      8
#define NR      16
#define NE      640000
#define TILE_M  128
#define MAX_TILES (NE / TILE_M + NR)          // 5016
#define HB_EDGES  8192
#define NHB ((NE + HB_EDGES - 1) / HB_EDGES)  // 79

#define TILE_BYTES 32768                      // 128 x 128 fp16, swizzled image

// ---------------- scratch (device globals; no allocs allowed) ----------------
__device__ __half g_h_hi[(size_t)N_NODES * HD];          // 12.8 MB
__device__ __half g_h_lo[(size_t)N_NODES * HD];          // 12.8 MB
// W prepacked per relation as the exact SMEM tile image (blocked-atom SW128)
__device__ unsigned char g_w_pk[(size_t)NR * TILE_BYTES];   // 512 KB
__device__ float g_h1[(size_t)N_NODES * HD];             // layer-1 output
__device__ int  g_sorted[NE];
__device__ int  g_hist[NR];
__device__ int  g_cursor[NR];
__device__ int4 g_tiles[MAX_TILES];                      // {rel, start, cnt, 0}
__device__ int  g_ntiles;

// ---------------------------------------------------------------------------
__device__ __forceinline__ void cp_async16_s(uint32_t s, const void* g)
{
    asm volatile("cp.async.ca.shared.global [%0], [%1], 16;\n" :: "r"(s), "l"(g));
}

// Blocked-atom SW128 byte offset for element (row, k) of a [128 x 128] b16
// K-major tile: atom = 8 rows x 64 elems (1024 B); atoms tile M first (16),
// then K (2). XOR source is purely row&7 -> ldmatrix conflict-free.
__device__ __forceinline__ uint32_t toff(int row, int k)
{
    uint32_t atom = (uint32_t)((row >> 3) + (k >> 6) * 16);
    uint32_t sw   = ((uint32_t)(k & 63) * 2) ^ (((uint32_t)row & 7) << 4);
    return atom * 1024 + ((uint32_t)row & 7) * 128 + sw;
}

#define LDSM_X4(r0, r1, r2, r3, addr)                                        \
    asm volatile("ldmatrix.sync.aligned.m8n8.x4.shared.b16 {%0,%1,%2,%3}, [%4];" \
                 : "=r"(r0), "=r"(r1), "=r"(r2), "=r"(r3) : "r"(addr))

__device__ __forceinline__ void mma16816(float c[4],
                                         uint32_t a0, uint32_t a1, uint32_t a2, uint32_t a3,
                                         uint32_t b0, uint32_t b1)
{
    asm volatile(
        "mma.sync.aligned.m16n8k16.row.col.f32.f16.f16.f32 "
        "{%0,%1,%2,%3}, {%4,%5,%6,%7}, {%8,%9}, {%0,%1,%2,%3};\n"
        : "+f"(c[0]), "+f"(c[1]), "+f"(c[2]), "+f"(c[3])
        : "r"(a0), "r"(a1), "r"(a2), "r"(a3), "r"(b0), "r"(b1));
}

// ---------------- bucketing: counting sort of edges by relation -------------
__global__ void k_zero_hist()
{
    if (threadIdx.x < NR) g_hist[threadIdx.x] = 0;
}

__global__ __launch_bounds__(256) void k_hist(const int* __restrict__ et)
{
    __shared__ int sh[NR];
    if (threadIdx.x < NR) sh[threadIdx.x] = 0;
    __syncthreads();
    int base = blockIdx.x * HB_EDGES;
    int end  = min(base + HB_EDGES, NE);
    for (int i = base + threadIdx.x; i < end; i += 256)
        atomicAdd(&sh[et[i]], 1);
    __syncthreads();
    if (threadIdx.x < NR) atomicAdd(&g_hist[threadIdx.x], sh[threadIdx.x]);
}

__global__ __launch_bounds__(256) void k_scan_tiles()
{
    __shared__ int off[NR + 1], tb[NR + 1];
    if (threadIdx.x == 0) {
        int acc = 0, t = 0;
        for (int r = 0; r < NR; r++) {
            off[r] = acc; tb[r] = t;
            g_cursor[r] = acc;
            int c = g_hist[r];
            acc += c;
            t += (c + TILE_M - 1) / TILE_M;
        }
        off[NR] = acc; tb[NR] = t;
        g_ntiles = t;
    }
    __syncthreads();
    int nt = tb[NR];
    for (int idx = threadIdx.x; idx < nt; idx += 256) {
        int r = 0;
        while (tb[r + 1] <= idx) r++;
        int local = idx - tb[r];
        int start = off[r] + local * TILE_M;
        int cnt   = min(TILE_M, off[r + 1] - start);
        g_tiles[idx] = make_int4(r, start, cnt, 0);
    }
}

__global__ __launch_bounds__(256) void k_place(const int* __restrict__ et)
{
    __shared__ int sh[NR], sbase[NR];
    if (threadIdx.x < NR) sh[threadIdx.x] = 0;
    __syncthreads();
    int base = blockIdx.x * HB_EDGES;
    int end  = min(base + HB_EDGES, NE);
    for (int i = base + threadIdx.x; i < end; i += 256)
        atomicAdd(&sh[et[i]], 1);
    __syncthreads();
    if (threadIdx.x < NR) {
        sbase[threadIdx.x] = atomicAdd(&g_cursor[threadIdx.x], sh[threadIdx.x]);
        sh[threadIdx.x] = 0;
    }
    __syncthreads();
    for (int i = base + threadIdx.x; i < end; i += 256) {
        int r = et[i];
        int p = sbase[r] + atomicAdd(&sh[r], 1);
        g_sorted[p] = i;
    }
}

// ---- W[r] = coef[r]·basis, packed fp16 as swizzled [o][k] tile image -------
__global__ __launch_bounds__(256) void k_fold_w(const float* __restrict__ basis,
                                                const float* __restrict__ coef)
{
    int r = blockIdx.x;
    __shared__ float cf[NB];
    if (threadIdx.x < NB) cf[threadIdx.x] = coef[r * NB + threadIdx.x];
    __syncthreads();
    unsigned char* wp = g_w_pk + (size_t)r * TILE_BYTES;
    for (int e = threadIdx.x; e < HD * HD; e += 256) {
        int k = e >> 7, o = e & 127;
        float acc = 0.f;
#pragma unroll
        for (int b = 0; b < NB; b++)
            acc = fmaf(cf[b], basis[((size_t)b * HD + k) * HD + o], acc);
        *(__half*)(wp + toff(o, k)) = __float2half_rn(acc);
    }
}

// ---------------- split node features to fp16 hi/lo (optional ReLU) ---------
template <bool RELU>
__global__ __launch_bounds__(256) void k_split_h(const float* __restrict__ x)
{
    int idx = blockIdx.x * 256 + threadIdx.x;
    if (idx < N_NODES * HD) {
        float v = x[idx];
        if (RELU) v = fmaxf(v, 0.f);
        __half hi = __float2half_rn(v);
        g_h_hi[idx] = hi;
        g_h_lo[idx] = __float2half_rn(v - __half2float(hi));
    }
}

// ---------------- out[n][o] = bias[o] ---------------------------------------
__global__ void init_bias_kernel(float* __restrict__ out,
                                 const float* __restrict__ bias)
{
    int idx = blockIdx.x * blockDim.x + threadIdx.x;
    if (idx < N_NODES * HD) out[idx] = bias[idx & (HD - 1)];
}

// ---------------------------------------------------------------------------
// Fused gather-GEMM-scatter. One block = one 128-edge tile of one relation.
//   C[128x128] = (Ah + Al)[src_tile] @ fp16(W[rel])^T    (2 mma products)
//   red.global.add.v4.f32(out[dst_i][:], C[i][:] * norm_i)
// 256 threads (8 warps 2x4), warp tile 64x32, K=128 single SMEM stage,
// SW128 blocked-atom tiles + ldmatrix.x4 fragments. 2 CTAs/SM.
// ---------------------------------------------------------------------------
__global__ __launch_bounds__(256, 2) void k_edge_gemm(
    const int* __restrict__ src, const int* __restrict__ dst,
    const float* __restrict__ norm, float* __restrict__ out)
{
    if ((int)blockIdx.x >= g_ntiles) return;
    int4 tl  = g_tiles[blockIdx.x];
    int  rel = tl.x, start = tl.y, cnt = tl.z;

    extern __shared__ char smem[];
    uint32_t base = (uint32_t)__cvta_generic_to_shared(smem);
    int*   srcv  = (int*)smem;
    int*   dstv  = (int*)(smem + 512);
    float* normv = (float*)(smem + 1024);
    uint32_t tiles_a = (base + 2048 + 1023) & ~1023u;   // 1024-aligned
    uint32_t sa_hi = tiles_a;
    uint32_t sa_lo = tiles_a + TILE_BYTES;
    uint32_t sw_t  = tiles_a + 2 * TILE_BYTES;

    const int tid  = threadIdx.x;
    const int lane = tid & 31;

    if (tid < 128) {
        if (tid < cnt) {
            int eid = g_sorted[start + tid];
            srcv[tid]  = src[eid];
            dstv[tid]  = dst[eid];
            normv[tid] = norm[eid];
        } else {
            srcv[tid] = 0; dstv[tid] = -1; normv[tid] = 0.f;
        }
    }
    __syncthreads();

    // ---- W tile: straight copy of prepacked swizzled image (32 KB)
    {
        const unsigned char* wp = g_w_pk + (size_t)rel * TILE_BYTES;
#pragma unroll
        for (int i = 0; i < 8; i++) {
            int off = tid * 16 + i * 4096;
            cp_async16_s(sw_t + off, wp + off);
        }
    }
    // ---- gather A rows into swizzled tiles (2 threads per row: hi/lo)
    {
        int row  = tid >> 1, half = tid & 1;
        const __half* gA = (half ? g_h_lo : g_h_hi) + (size_t)srcv[row] * HD;
        uint32_t      sA = half ? sa_lo : sa_hi;
#pragma unroll
        for (int c = 0; c < 16; c++)
            cp_async16_s(sA + toff(row, c * 8), gA + c * 8);
    }
    asm volatile("cp.async.commit_group;\n" ::: "memory");
    asm volatile("cp.async.wait_group 0;\n" ::: "memory");
    __syncthreads();

    const int warp = tid >> 5;
    const int wm = warp >> 2, wn = warp & 3;     // warp tile: rows wm*64, cols wn*32
    const int mid = lane >> 3, rin = lane & 7;   // ldmatrix group / row-in-group

    float c[4][4][4];
#pragma unroll
    for (int mt = 0; mt < 4; mt++)
#pragma unroll
        for (int nt = 0; nt < 4; nt++)
#pragma unroll
            for (int q = 0; q < 4; q++) c[mt][nt][q] = 0.f;

#pragma unroll
    for (int ks = 0; ks < HD; ks += 16) {
        // A fragments: groups (rows+0,k0)(rows+8,k0)(rows+0,k8)(rows+8,k8)
        uint32_t ah[4][4], al[4][4];
        int ka = ks + ((mid >> 1) << 3);
        int ra = ((mid & 1) << 3) + rin;
#pragma unroll
        for (int mt = 0; mt < 4; mt++) {
            uint32_t rel_off = toff(wm * 64 + mt * 16 + ra, ka);
            LDSM_X4(ah[mt][0], ah[mt][1], ah[mt][2], ah[mt][3], sa_hi + rel_off);
            LDSM_X4(al[mt][0], al[mt][1], al[mt][2], al[mt][3], sa_lo + rel_off);
        }
        // B fragments: groups (nt,k0)(nt,k8)(nt+1,k0)(nt+1,k8)
        uint32_t bb[2][4];
        int kb = ks + ((mid & 1) << 3);
#pragma unroll
        for (int p = 0; p < 2; p++) {
            int nc = wn * 32 + p * 16 + ((mid >> 1) << 3) + rin;
            LDSM_X4(bb[p][0], bb[p][1], bb[p][2], bb[p][3], sw_t + toff(nc, kb));
        }
#pragma unroll
        for (int mt = 0; mt < 4; mt++)
#pragma unroll
            for (int nt = 0; nt < 4; nt++) {
                uint32_t b0 = bb[nt >> 1][(nt & 1) * 2];
                uint32_t b1 = bb[nt >> 1][(nt & 1) * 2 + 1];
                mma16816(c[mt][nt], ah[mt][0], ah[mt][1], ah[mt][2], ah[mt][3], b0, b1);
                mma16816(c[mt][nt], al[mt][0], al[mt][1], al[mt][2], al[mt][3], b0, b1);
            }
    }

    // ---- scatter epilogue with vectorized reductions.
    // Fragment: thread (gq, t) holds rows (row0, row0+8), cols 2t..2t+1 per nt.
    // Pair-transpose via shfl_xor(1): even lanes assemble 4 consecutive row0
    // cols, odd lanes 4 consecutive row1 cols -> one red.global.add.v4.f32.
    {
        const int gq = lane >> 2, t = lane & 3;
        const bool even = (t & 1) == 0;
#pragma unroll
        for (int mt = 0; mt < 4; mt++) {
            int row0 = wm * 64 + mt * 16 + gq;
            int rown = even ? row0 : row0 + 8;
            int   d  = dstv[rown];
            float nm = normv[rown];
#pragma unroll
            for (int nt = 0; nt < 4; nt++) {
                float e0 = __shfl_xor_sync(0xFFFFFFFFu, c[mt][nt][0], 1);
                float e1 = __shfl_xor_sync(0xFFFFFFFFu, c[mt][nt][1], 1);
                float e2 = __shfl_xor_sync(0xFFFFFFFFu, c[mt][nt][2], 1);
                float e3 = __shfl_xor_sync(0xFFFFFFFFu, c[mt][nt][3], 1);
                float v0, v1, v2, v3;
                int col;
                if (even) {  // row0: own cols 2t,2t+1 + partner cols 2t+2,2t+3
                    v0 = c[mt][nt][0]; v1 = c[mt][nt][1]; v2 = e0; v3 = e1;
                    col = wn * 32 + nt * 8 + t * 2;
                } else {     // row1: partner cols 2t-2,2t-1 + own cols 2t,2t+1
                    v0 = e2; v1 = e3; v2 = c[mt][nt][2]; v3 = c[mt][nt][3];
                    col = wn * 32 + nt * 8 + (t - 1) * 2;
                }
                if (d >= 0) {
                    float* p = out + (size_t)d * HD + col;
                    asm volatile(
                        "red.global.add.v4.f32 [%0], {%1,%2,%3,%4};"
                        :: "l"(p), "f"(v0 * nm), "f"(v1 * nm),
                           "f"(v2 * nm), "f"(v3 * nm)
                        : "memory");
                }
            }
        }
    }
}

// ---------------------------------------------------------------------------
// kernel_launch
// Inputs: 0:h 1:norm 2:src 3:dst 4:etype 5:V1 6:coef1 7:bias1 8:V2 9:coef2 10:bias2
// ---------------------------------------------------------------------------
extern "C" void kernel_launch(void* const* d_in, const int* in_sizes, int n_in,
                              void* d_out, int out_size)
{
    const float* h     = (const float*)d_in[0];
    const float* norm  = (const float*)d_in[1];
    const int*   src   = (const int*)d_in[2];
    const int*   dst   = (const int*)d_in[3];
    const int*   etype = (const int*)d_in[4];
    const float* V1    = (const float*)d_in[5];
    const float* coef1 = (const float*)d_in[6];
    const float* bias1 = (const float*)d_in[7];
    const float* V2    = (const float*)d_in[8];
    const float* coef2 = (const float*)d_in[9];
    const float* bias2 = (const float*)d_in[10];
    float*       out   = (float*)d_out;

    float* h1; cudaGetSymbolAddress((void**)&h1, g_h1);

    static int smem_set = 0;
    const int GEMM_SMEM = 2048 + 1024 + 3 * TILE_BYTES;   // ~99 KB -> 2 CTAs/SM
    if (!smem_set) {
        cudaFuncSetAttribute(k_edge_gemm,
                             cudaFuncAttributeMaxDynamicSharedMemorySize, GEMM_SMEM);
        smem_set = 1;
    }

    int nh_elems  = N_NODES * HD;
    int elem_grid = (nh_elems + 255) / 256;

    // ---- bucket edges by relation (shared by both layers)
    k_zero_hist<<<1, 32>>>();
    k_hist<<<NHB, 256>>>(etype);
    k_scan_tiles<<<1, 256>>>();
    k_place<<<NHB, 256>>>(etype);

    // ---- Layer 1
    k_fold_w<<<NR, 256>>>(V1, coef1);
    k_split_h<false><<<elem_grid, 256>>>(h);
    init_bias_kernel<<<elem_grid, 256>>>(h1, bias1);
    k_edge_gemm<<<MAX_TILES, 256, GEMM_SMEM>>>(src, dst, norm, h1);

    // ---- Layer 2
    k_fold_w<<<NR, 256>>>(V2, coef2);
    k_split_h<true><<<elem_grid, 256>>>(h1);
    init_bias_kernel<<<elem_grid, 256>>>(out, bias2);
    k_edge_gemm<<<MAX_TILES, 256, GEMM_SMEM>>>(src, dst, norm, out);
}